// round 16
// baseline (speedup 1.0000x reference)
#include <cuda_runtime.h>
#include <cuda_fp16.h>
#include <stdint.h>

#define NUM_USERS 100000
#define N_NODES   150000
#define D         64
#define D4        16          // float4 per fp32 row
#define DH2       16          // uint2 (=4 halfs) per fp16 row
#define E_EDGES   1200000
#define NBIN      64

// ---------------- device scratch (allocation-free) ----------------
__device__ uint2 g_s0[N_NODES * DH2];      // x~0 = emb * s_r   (fp16, scaled)
__device__ uint2 g_s1[N_NODES * DH2];      // x~1 = x1 * s_r
__device__ uint2 g_s2[N_NODES * DH2];      // x~2 = x2 * s_r
__device__ int   g_degi[2 * N_NODES];      // [0,N): deg_row  [N,2N): deg_col
__device__ float g_inv [2 * N_NODES];      // [0,N): s_r (=rsqrt or 1)  [N,2N): inv_c (=rsqrt or 0)
__device__ float g_rs  [N_NODES];          // 1/s_r  (recover factor)
__device__ int   g_offs[N_NODES];          // CSR start per dst node
__device__ int   g_cursor[N_NODES];        // fill cursors
__device__ int   g_csr[E_EDGES + 4];       // src row only (+4 pad: unpredicated 4-wide prefetch)
__device__ int   g_total;                  // range allocator
__device__ int   g_hist[NBIN];             // degree histogram
__device__ int   g_bincur[NBIN];           // bin cursors (descending layout)
__device__ int   g_perm[N_NODES];          // nodes ordered by deg_col DESC

// ---------------- helpers ----------------

__device__ __forceinline__ void acc_h2(unsigned long long& acc, unsigned h2) {
    asm("{\n\t"
        ".reg .b16 lo, hi;\n\t"
        ".reg .f32 f0, f1;\n\t"
        ".reg .b64 v;\n\t"
        "mov.b32 {lo, hi}, %1;\n\t"
        "cvt.f32.f16 f0, lo;\n\t"
        "cvt.f32.f16 f1, hi;\n\t"
        "mov.b64 v, {f0, f1};\n\t"
        "add.rn.f32x2 %0, %0, v;\n\t"
        "}" : "+l"(acc) : "r"(h2));
}

__device__ __forceinline__ float2 unpack_x2(unsigned long long a) {
    float2 r;
    asm("mov.b64 {%0, %1}, %2;" : "=f"(r.x), "=f"(r.y) : "l"(a));
    return r;
}

__device__ __forceinline__ uint2 pack_h4(float2 a, float2 b) {
    __half2 h0 = __float22half2_rn(a);
    __half2 h1 = __float22half2_rn(b);
    uint2 o;
    o.x = *reinterpret_cast<unsigned*>(&h0);
    o.y = *reinterpret_cast<unsigned*>(&h1);
    return o;
}

__device__ __forceinline__ float2 unpack_h2(unsigned h) {
    return __half22float2(*reinterpret_cast<__half2*>(&h));
}

// ---------------- setup kernels ----------------

__global__ void k_deg(const int* __restrict__ row, const int* __restrict__ col) {
    int e = blockIdx.x * blockDim.x + threadIdx.x;
    if (e == 0) g_total = 0;
    if (e < NBIN) g_hist[e] = 0;
    if (e < E_EDGES) {
        atomicAdd(&g_degi[row[e]], 1);
        atomicAdd(&g_degi[N_NODES + col[e]], 1);
    }
}

// Fused: scale factors + CSR range allocation + degree histogram.
// s_r = rsqrt(deg_row) with deg_row==0 -> 1 (invertible; such nodes are never
// gathered, so the value is gather-inert). g_rs = 1/s_r recovers true values.
__global__ void k_alloc() {
    __shared__ int s_wtot[8];
    __shared__ int s_base;
    __shared__ int s_hist[NBIN];
    int n    = blockIdx.x * 256 + threadIdx.x;
    int lane = threadIdx.x & 31;
    int wid  = threadIdx.x >> 5;
    if (threadIdx.x < NBIN) s_hist[threadIdx.x] = 0;
    __syncthreads();

    int dc = 0;
    if (n < N_NODES) {
        int dr = g_degi[n];
        dc     = g_degi[N_NODES + n];
        g_inv[n]           = (dr > 0) ? rsqrtf((float)dr) : 1.0f;
        g_rs [n]           = (dr > 0) ? sqrtf((float)dr)  : 1.0f;
        g_inv[N_NODES + n] = (dc > 0) ? rsqrtf((float)dc) : 0.0f;
        atomicAdd(&s_hist[min(dc, NBIN - 1)], 1);
    }

    int x = dc;                               // warp inclusive scan
    #pragma unroll
    for (int o = 1; o < 32; o <<= 1) {
        int y = __shfl_up_sync(0xffffffffu, x, o);
        if (lane >= o) x += y;
    }
    if (lane == 31) s_wtot[wid] = x;
    __syncthreads();
    if (wid == 0) {
        int v = (lane < 8) ? s_wtot[lane] : 0;
        #pragma unroll
        for (int o = 1; o < 8; o <<= 1) {
            int y = __shfl_up_sync(0xffffffffu, v, o);
            if (lane >= o) v += y;
        }
        if (lane < 8) s_wtot[lane] = v;
        if (lane == 7) s_base = atomicAdd(&g_total, v);
    }
    __syncthreads();
    int base = s_base + (wid > 0 ? s_wtot[wid - 1] : 0);
    if (n < N_NODES) {
        int excl = base + x - dc;
        g_offs[n]   = excl;
        g_cursor[n] = excl;
    }
    if (threadIdx.x < NBIN && s_hist[threadIdx.x] > 0)
        atomicAdd(&g_hist[threadIdx.x], s_hist[threadIdx.x]);
}

// 64-bin scan -> DESCENDING bin bases (heavy warps first).
__global__ void k_scan() {
    __shared__ int s[NBIN];
    int i = threadIdx.x;
    int v = g_hist[i];
    s[i] = v;
    __syncthreads();
    for (int o = 1; o < NBIN; o <<= 1) {
        int t = (i >= o) ? s[i - o] : 0;
        __syncthreads();
        s[i] += t;
        __syncthreads();
    }
    g_bincur[i] = N_NODES - s[i];
}

// Block-aggregated counting-sort scatter.
__global__ void k_perm() {
    __shared__ int s_cnt[NBIN];
    __shared__ int s_base[NBIN];
    int i = blockIdx.x * 256 + threadIdx.x;
    if (threadIdx.x < NBIN) s_cnt[threadIdx.x] = 0;
    __syncthreads();
    int b = 0, lr = 0;
    bool ok = (i < N_NODES);
    if (ok) {
        b  = min(g_degi[N_NODES + i], NBIN - 1);
        lr = atomicAdd(&s_cnt[b], 1);
    }
    __syncthreads();
    if (threadIdx.x < NBIN) {
        int c = s_cnt[threadIdx.x];
        s_base[threadIdx.x] = c ? atomicAdd(&g_bincur[threadIdx.x], c) : 0;
    }
    __syncthreads();
    if (ok) g_perm[s_base[b] + lr] = i;
}

// Fused: CSR fill (first 1.2M threads) + emb*s_r fp16 convert (all 2.4M).
__global__ void k_fillcvt(const int* __restrict__ row, const int* __restrict__ col,
                          const float4* __restrict__ emb) {
    int i = blockIdx.x * blockDim.x + threadIdx.x;
    if (i < E_EDGES) {
        int slot = atomicAdd(&g_cursor[col[i]], 1);
        g_csr[slot] = row[i];
    }
    if (i < N_NODES * D4) {
        int n = i >> 4;
        float w = __ldg(&g_inv[n]);
        float4 v = __ldg(&emb[i]);
        g_s0[i] = pack_h4(make_float2(v.x * w, v.y * w),
                          make_float2(v.z * w, v.w * w));
    }
}

// ---------------- propagation layer ----------------
// Degree-sorted (desc) 16-lane-per-node pull, 4-wide unpredicated pipeline
// (csr padded by 4). Invariant: at loop index j, r[k] == csr[beg+j+k].
// FINAL=0: dstS = half(acc * inv_c * s_r)           (scaled only; true value
//                                                    recoverable via g_rs)
// FINAL=1: out = (emb + s1*rs + s2*rs + acc*inv_c) * 0.25
template<int FINAL>
__global__ void k_layerh(const uint2* __restrict__ src,
                         uint2* __restrict__ dstS,
                         const float4* __restrict__ emb,
                         const uint2* __restrict__ s1,
                         const uint2* __restrict__ s2,
                         float4* __restrict__ out) {
    int t = blockIdx.x * blockDim.x + threadIdx.x;
    int slot = t >> 4;
    int q    = t & 15;
    if (slot >= N_NODES) return;
    int n = __ldg(&g_perm[slot]);

    int beg = __ldg(&g_offs[n]);
    int d   = __ldg(&g_degi[N_NODES + n]);

    unsigned long long a0 = 0ull, a1 = 0ull;   // packed f32x2 accumulators

    int r0 = 0, r1 = 0, r2 = 0, r3 = 0;
    if (d > 0) {                               // beg+1..3 safe: csr has +4 pad
        r0 = __ldg(&g_csr[beg]);
        r1 = __ldg(&g_csr[beg + 1]);
        r2 = __ldg(&g_csr[beg + 2]);
        r3 = __ldg(&g_csr[beg + 3]);
    }
    int j = 0;
    for (; j + 3 < d; j += 4) {
        uint2 v0 = __ldg(&src[r0 * DH2 + q]);
        uint2 v1 = __ldg(&src[r1 * DH2 + q]);
        uint2 v2 = __ldg(&src[r2 * DH2 + q]);
        uint2 v3 = __ldg(&src[r3 * DH2 + q]);
        r0 = __ldg(&g_csr[beg + j + 4]);       // unconditional: pad covers it
        r1 = __ldg(&g_csr[beg + j + 5]);
        r2 = __ldg(&g_csr[beg + j + 6]);
        r3 = __ldg(&g_csr[beg + j + 7]);
        acc_h2(a0, v0.x); acc_h2(a1, v0.y);
        acc_h2(a0, v1.x); acc_h2(a1, v1.y);
        acc_h2(a0, v2.x); acc_h2(a1, v2.y);
        acc_h2(a0, v3.x); acc_h2(a1, v3.y);
    }
    // tail (<=3 edges): r0..r2 hold csr[beg+j .. beg+j+2] by the invariant
    if (j < d) {
        uint2 v = __ldg(&src[r0 * DH2 + q]);
        acc_h2(a0, v.x); acc_h2(a1, v.y);
    }
    if (j + 1 < d) {
        uint2 v = __ldg(&src[r1 * DH2 + q]);
        acc_h2(a0, v.x); acc_h2(a1, v.y);
    }
    if (j + 2 < d) {
        uint2 v = __ldg(&src[r2 * DH2 + q]);
        acc_h2(a0, v.x); acc_h2(a1, v.y);
    }

    float inv_c = __ldg(&g_inv[N_NODES + n]);
    float2 f0 = unpack_x2(a0);
    float2 f1 = unpack_x2(a1);
    f0.x *= inv_c; f0.y *= inv_c; f1.x *= inv_c; f1.y *= inv_c;   // true x_k

    int oi = n * DH2 + q;
    if (FINAL == 0) {
        float s_r = __ldg(&g_inv[n]);
        dstS[oi] = pack_h4(make_float2(f0.x * s_r, f0.y * s_r),
                           make_float2(f1.x * s_r, f1.y * s_r));
    } else {
        float rs = __ldg(&g_rs[n]);            // recover true x1, x2
        float4 em = __ldg(&emb[oi]);
        uint2 va = __ldg(&s1[oi]);
        uint2 vb = __ldg(&s2[oi]);
        float2 fa0 = unpack_h2(va.x), fa1 = unpack_h2(va.y);
        float2 fb0 = unpack_h2(vb.x), fb1 = unpack_h2(vb.y);
        const float s = 0.25f;
        out[oi] = make_float4((em.x + (fa0.x + fb0.x) * rs + f0.x) * s,
                              (em.y + (fa0.y + fb0.y) * rs + f0.y) * s,
                              (em.z + (fa1.x + fb1.x) * rs + f1.x) * s,
                              (em.w + (fa1.y + fb1.y) * rs + f1.y) * s);
    }
}

// ---------------- launch ----------------

extern "C" void kernel_launch(void* const* d_in, const int* in_sizes, int n_in,
                              void* d_out, int out_size) {
    const int*   edge = (const int*)d_in[0];   // [2, E]
    const float* emb  = (const float*)d_in[1]; // [N, 64]
    float*       out  = (float*)d_out;

    const int* row = edge;
    const int* col = edge + E_EDGES;

    uint2* s0p; cudaGetSymbolAddress((void**)&s0p, g_s0);
    uint2* s1p; cudaGetSymbolAddress((void**)&s1p, g_s1);
    uint2* s2p; cudaGetSymbolAddress((void**)&s2p, g_s2);
    int*  degp; cudaGetSymbolAddress((void**)&degp, g_degi);

    const int TB = 256;
    const int gE   = (E_EDGES + TB - 1) / TB;
    const int gN   = (N_NODES + TB - 1) / TB;
    const int gBig = (N_NODES * D4 + TB - 1) / TB;   // 2.4M threads
    const int gLyr = (N_NODES * 16 + TB - 1) / TB;

    // CSR build + degree sort (descending) + pre-scaled fp16 conversion
    cudaMemsetAsync(degp, 0, 2 * N_NODES * sizeof(int));
    k_deg<<<gE, TB>>>(row, col);
    k_alloc<<<gN, TB>>>();
    k_scan<<<1, NBIN>>>();
    k_perm<<<gN, TB>>>();
    k_fillcvt<<<gBig, TB>>>(row, col, (const float4*)emb);

    // 3 propagation layers; out accumulation fused into final epilogue
    k_layerh<0><<<gLyr, TB>>>(s0p, s1p, nullptr, nullptr, nullptr, nullptr);
    k_layerh<0><<<gLyr, TB>>>(s1p, s2p, nullptr, nullptr, nullptr, nullptr);
    k_layerh<1><<<gLyr, TB>>>(s2p, nullptr,
                              (const float4*)emb, s1p, s2p, (float4*)out);
}

// round 17
// speedup vs baseline: 1.0961x; 1.0961x over previous
#include <cuda_runtime.h>
#include <cuda_fp16.h>
#include <stdint.h>

#define NUM_USERS 100000
#define N_NODES   150000
#define D         64
#define D4        16          // float4 per fp32 row
#define DH2       16          // uint2 (=4 halfs) per fp16 row
#define E_EDGES   1200000
#define NBIN      64

// ---------------- device scratch (allocation-free) ----------------
__device__ uint2 g_s0[N_NODES * DH2];      // x~0 = emb * s_r   (fp16, scaled)
__device__ uint2 g_s1[N_NODES * DH2];      // x~1 = x1 * s_r
__device__ uint2 g_s2[N_NODES * DH2];      // x~2 = x2 * s_r
__device__ int   g_degi[2 * N_NODES];      // [0,N): deg_row  [N,2N): deg_col
__device__ float g_inv [2 * N_NODES];      // [0,N): s_r (=rsqrt or 1)  [N,2N): inv_c (=rsqrt or 0)
__device__ float g_rs  [N_NODES];          // 1/s_r  (recover factor)
__device__ int   g_offs[N_NODES];          // CSR start per dst node
__device__ int   g_cursor[N_NODES];        // fill cursors
__device__ int   g_csr[E_EDGES + 2];       // src row only (+2 pad: unpredicated 2-wide prefetch)
__device__ int   g_total;                  // range allocator
__device__ int   g_hist[NBIN];             // degree histogram
__device__ int   g_bincur[NBIN];           // bin cursors (descending layout)
__device__ int   g_perm[N_NODES];          // nodes ordered by deg_col DESC

// ---------------- helpers ----------------

__device__ __forceinline__ void acc_h2(unsigned long long& acc, unsigned h2) {
    asm("{\n\t"
        ".reg .b16 lo, hi;\n\t"
        ".reg .f32 f0, f1;\n\t"
        ".reg .b64 v;\n\t"
        "mov.b32 {lo, hi}, %1;\n\t"
        "cvt.f32.f16 f0, lo;\n\t"
        "cvt.f32.f16 f1, hi;\n\t"
        "mov.b64 v, {f0, f1};\n\t"
        "add.rn.f32x2 %0, %0, v;\n\t"
        "}" : "+l"(acc) : "r"(h2));
}

__device__ __forceinline__ float2 unpack_x2(unsigned long long a) {
    float2 r;
    asm("mov.b64 {%0, %1}, %2;" : "=f"(r.x), "=f"(r.y) : "l"(a));
    return r;
}

__device__ __forceinline__ uint2 pack_h4(float2 a, float2 b) {
    __half2 h0 = __float22half2_rn(a);
    __half2 h1 = __float22half2_rn(b);
    uint2 o;
    o.x = *reinterpret_cast<unsigned*>(&h0);
    o.y = *reinterpret_cast<unsigned*>(&h1);
    return o;
}

__device__ __forceinline__ float2 unpack_h2(unsigned h) {
    return __half22float2(*reinterpret_cast<__half2*>(&h));
}

// ---------------- setup kernels ----------------

__global__ void k_deg(const int* __restrict__ row, const int* __restrict__ col) {
    int e = blockIdx.x * blockDim.x + threadIdx.x;
    if (e == 0) g_total = 0;
    if (e < NBIN) g_hist[e] = 0;
    if (e < E_EDGES) {
        atomicAdd(&g_degi[row[e]], 1);
        atomicAdd(&g_degi[N_NODES + col[e]], 1);
    }
}

// Fused: scale factors + CSR range allocation + degree histogram.
// s_r = rsqrt(deg_row), with deg_row==0 -> 1 (invertible; zero-deg rows are
// never gathered, so the substitute value is gather-inert).
__global__ void k_alloc() {
    __shared__ int s_wtot[8];
    __shared__ int s_base;
    __shared__ int s_hist[NBIN];
    int n    = blockIdx.x * 256 + threadIdx.x;
    int lane = threadIdx.x & 31;
    int wid  = threadIdx.x >> 5;
    if (threadIdx.x < NBIN) s_hist[threadIdx.x] = 0;
    __syncthreads();

    int dc = 0;
    if (n < N_NODES) {
        int dr = g_degi[n];
        dc     = g_degi[N_NODES + n];
        g_inv[n]           = (dr > 0) ? rsqrtf((float)dr) : 1.0f;
        g_rs [n]           = (dr > 0) ? sqrtf((float)dr)  : 1.0f;
        g_inv[N_NODES + n] = (dc > 0) ? rsqrtf((float)dc) : 0.0f;
        atomicAdd(&s_hist[min(dc, NBIN - 1)], 1);
    }

    int x = dc;                               // warp inclusive scan
    #pragma unroll
    for (int o = 1; o < 32; o <<= 1) {
        int y = __shfl_up_sync(0xffffffffu, x, o);
        if (lane >= o) x += y;
    }
    if (lane == 31) s_wtot[wid] = x;
    __syncthreads();
    if (wid == 0) {
        int v = (lane < 8) ? s_wtot[lane] : 0;
        #pragma unroll
        for (int o = 1; o < 8; o <<= 1) {
            int y = __shfl_up_sync(0xffffffffu, v, o);
            if (lane >= o) v += y;
        }
        if (lane < 8) s_wtot[lane] = v;
        if (lane == 7) s_base = atomicAdd(&g_total, v);
    }
    __syncthreads();
    int base = s_base + (wid > 0 ? s_wtot[wid - 1] : 0);
    if (n < N_NODES) {
        int excl = base + x - dc;
        g_offs[n]   = excl;
        g_cursor[n] = excl;
    }
    if (threadIdx.x < NBIN && s_hist[threadIdx.x] > 0)
        atomicAdd(&g_hist[threadIdx.x], s_hist[threadIdx.x]);
}

// 64-bin scan -> DESCENDING bin bases (heavy warps first).
__global__ void k_scan() {
    __shared__ int s[NBIN];
    int i = threadIdx.x;
    int v = g_hist[i];
    s[i] = v;
    __syncthreads();
    for (int o = 1; o < NBIN; o <<= 1) {
        int t = (i >= o) ? s[i - o] : 0;
        __syncthreads();
        s[i] += t;
        __syncthreads();
    }
    g_bincur[i] = N_NODES - s[i];
}

// Block-aggregated counting-sort scatter.
__global__ void k_perm() {
    __shared__ int s_cnt[NBIN];
    __shared__ int s_base[NBIN];
    int i = blockIdx.x * 256 + threadIdx.x;
    if (threadIdx.x < NBIN) s_cnt[threadIdx.x] = 0;
    __syncthreads();
    int b = 0, lr = 0;
    bool ok = (i < N_NODES);
    if (ok) {
        b  = min(g_degi[N_NODES + i], NBIN - 1);
        lr = atomicAdd(&s_cnt[b], 1);
    }
    __syncthreads();
    if (threadIdx.x < NBIN) {
        int c = s_cnt[threadIdx.x];
        s_base[threadIdx.x] = c ? atomicAdd(&g_bincur[threadIdx.x], c) : 0;
    }
    __syncthreads();
    if (ok) g_perm[s_base[b] + lr] = i;
}

// Fused: CSR fill (first 1.2M threads) + emb*s_r fp16 convert (all 2.4M).
__global__ void k_fillcvt(const int* __restrict__ row, const int* __restrict__ col,
                          const float4* __restrict__ emb) {
    int i = blockIdx.x * blockDim.x + threadIdx.x;
    if (i < E_EDGES) {
        int slot = atomicAdd(&g_cursor[col[i]], 1);
        g_csr[slot] = row[i];
    }
    if (i < N_NODES * D4) {
        int n = i >> 4;
        float w = __ldg(&g_inv[n]);
        float4 v = __ldg(&emb[i]);
        g_s0[i] = pack_h4(make_float2(v.x * w, v.y * w),
                          make_float2(v.z * w, v.w * w));
    }
}

// ---------------- propagation layer ----------------
// Degree-sorted (desc) 16-lane-per-node pull. PROVEN 2-wide unpredicated
// pipeline (csr padded by 2): two vector gathers + two record prefetches in
// flight; single-predicate odd tail.
// FINAL=0: dstS = half(acc * inv_c * s_r)     (scaled only; true value via g_rs)
// FINAL=1: out = (emb + (s1 + s2)*rs + acc*inv_c) * 0.25
template<int FINAL>
__global__ void k_layerh(const uint2* __restrict__ src,
                         uint2* __restrict__ dstS,
                         const float4* __restrict__ emb,
                         const uint2* __restrict__ s1,
                         const uint2* __restrict__ s2,
                         float4* __restrict__ out) {
    int t = blockIdx.x * blockDim.x + threadIdx.x;
    int slot = t >> 4;
    int q    = t & 15;
    if (slot >= N_NODES) return;
    int n = __ldg(&g_perm[slot]);

    int beg = __ldg(&g_offs[n]);
    int d   = __ldg(&g_degi[N_NODES + n]);

    unsigned long long a0 = 0ull, a1 = 0ull;   // packed f32x2 accumulators

    int r0 = 0, r1 = 0;
    if (d > 0) {                               // beg+1 safe: csr has +2 pad
        r0 = __ldg(&g_csr[beg]);
        r1 = __ldg(&g_csr[beg + 1]);
    }
    int j = 0;
    for (; j + 1 < d; j += 2) {
        uint2 v0 = __ldg(&src[r0 * DH2 + q]);
        uint2 v1 = __ldg(&src[r1 * DH2 + q]);
        r0 = __ldg(&g_csr[beg + j + 2]);       // unconditional: pad covers it
        r1 = __ldg(&g_csr[beg + j + 3]);
        acc_h2(a0, v0.x);
        acc_h2(a1, v0.y);
        acc_h2(a0, v1.x);
        acc_h2(a1, v1.y);
    }
    if (j < d) {                               // odd tail: record sits in r0
        uint2 v0 = __ldg(&src[r0 * DH2 + q]);
        acc_h2(a0, v0.x);
        acc_h2(a1, v0.y);
    }

    float inv_c = __ldg(&g_inv[N_NODES + n]);
    float2 f0 = unpack_x2(a0);
    float2 f1 = unpack_x2(a1);
    f0.x *= inv_c; f0.y *= inv_c; f1.x *= inv_c; f1.y *= inv_c;   // true x_k

    int oi = n * DH2 + q;
    if (FINAL == 0) {
        float s_r = __ldg(&g_inv[n]);
        dstS[oi] = pack_h4(make_float2(f0.x * s_r, f0.y * s_r),
                           make_float2(f1.x * s_r, f1.y * s_r));
    } else {
        float rs = __ldg(&g_rs[n]);            // recover true x1, x2
        float4 em = __ldg(&emb[oi]);
        uint2 va = __ldg(&s1[oi]);
        uint2 vb = __ldg(&s2[oi]);
        float2 fa0 = unpack_h2(va.x), fa1 = unpack_h2(va.y);
        float2 fb0 = unpack_h2(vb.x), fb1 = unpack_h2(vb.y);
        const float s = 0.25f;
        out[oi] = make_float4((em.x + (fa0.x + fb0.x) * rs + f0.x) * s,
                              (em.y + (fa0.y + fb0.y) * rs + f0.y) * s,
                              (em.z + (fa1.x + fb1.x) * rs + f1.x) * s,
                              (em.w + (fa1.y + fb1.y) * rs + f1.y) * s);
    }
}

// ---------------- launch ----------------

extern "C" void kernel_launch(void* const* d_in, const int* in_sizes, int n_in,
                              void* d_out, int out_size) {
    const int*   edge = (const int*)d_in[0];   // [2, E]
    const float* emb  = (const float*)d_in[1]; // [N, 64]
    float*       out  = (float*)d_out;

    const int* row = edge;
    const int* col = edge + E_EDGES;

    uint2* s0p; cudaGetSymbolAddress((void**)&s0p, g_s0);
    uint2* s1p; cudaGetSymbolAddress((void**)&s1p, g_s1);
    uint2* s2p; cudaGetSymbolAddress((void**)&s2p, g_s2);
    int*  degp; cudaGetSymbolAddress((void**)&degp, g_degi);

    const int TB = 256;
    const int gE   = (E_EDGES + TB - 1) / TB;
    const int gN   = (N_NODES + TB - 1) / TB;
    const int gBig = (N_NODES * D4 + TB - 1) / TB;   // 2.4M threads
    const int gLyr = (N_NODES * 16 + TB - 1) / TB;

    // CSR build + degree sort (descending) + pre-scaled fp16 conversion
    cudaMemsetAsync(degp, 0, 2 * N_NODES * sizeof(int));
    k_deg<<<gE, TB>>>(row, col);
    k_alloc<<<gN, TB>>>();
    k_scan<<<1, NBIN>>>();
    k_perm<<<gN, TB>>>();
    k_fillcvt<<<gBig, TB>>>(row, col, (const float4*)emb);

    // 3 propagation layers; out accumulation fused into final epilogue
    k_layerh<0><<<gLyr, TB>>>(s0p, s1p, nullptr, nullptr, nullptr, nullptr);
    k_layerh<0><<<gLyr, TB>>>(s1p, s2p, nullptr, nullptr, nullptr, nullptr);
    k_layerh<1><<<gLyr, TB>>>(s2p, nullptr,
                              (const float4*)emb, s1p, s2p, (float4*)out);
}